// round 14
// baseline (speedup 1.0000x reference)
#include <cuda_runtime.h>
#include <cuda_bf16.h>
#include <cstddef>

// FM layer:
//   idx[b,j] = N_DENSE + j*PER_FIELD + sparse[b,j]
//   first[b] = w0 + dense[b,:]·w[:13] + sum_j w[idx[b,j]]
//   e_k[b]   = dense[b,:]·V[k,:13] + sum_j V[k, idx[b,j]]
//   sq_k[b]  = (dense[b,:]^2)·(V[k,:13]^2) + sum_j V[k, idx[b,j]]^2
//   out[b]   = first[b] + 0.5 * sum_k (e_k^2 - sq_k)
//
// Inputs (metadata order):
//   d_in[0] dense  f32 [4096,13]
//   d_in[1] sparse i32 [4096,26]
//   d_in[2] w0     f32 [1]
//   d_in[3] w      f32 [2600013,1]
//   d_in[4] V      f32 [16,2600013]
// Output: f32 [4096,1]
//
// Layout: one warp per batch row. lane = (half, k): k = lane&15 selects the
// latent dim; half = lane>>4 selects fields [0,13) or [13,26). The distinct
// gathered working set (~87MB of V/w lines) fits L2 (126MB) and is identical
// every graph replay -> evict_last cache policy keeps it L2-resident so
// steady-state replays run in the L2-hit regime.

#define FM_BATCH     4096
#define FM_NDENSE    13
#define FM_NFIELDS   26
#define FM_PERFIELD  100000
#define FM_FEATNUM   2600013
#define FM_K         16

// evict_last policy handle (fraction 1.0 -> all lines set to last-evict)
__device__ __forceinline__ unsigned long long mk_policy_keep() {
    unsigned long long pol;
    asm("createpolicy.fractional.L2::evict_last.b64 %0, 1.0;" : "=l"(pol));
    return pol;
}

// L2-resident gather: non-coherent load with evict_last cache policy.
__device__ __forceinline__ float ldg_keep(const float* p, unsigned long long pol) {
    float v;
    asm("ld.global.nc.L2::cache_hint.f32 %0, [%1], %2;"
        : "=f"(v) : "l"(p), "l"(pol));
    return v;
}

__global__ __launch_bounds__(128, 8)
void fm_layer_kernel(const float* __restrict__ dense,
                     const int*   __restrict__ sparse,
                     const float* __restrict__ w0,
                     const float* __restrict__ w,
                     const float* __restrict__ V,
                     float*       __restrict__ out)
{
    const int gt   = blockIdx.x * blockDim.x + threadIdx.x;
    const int b    = gt >> 5;           // one warp per batch row
    const int lane = gt & 31;
    const int k    = lane & 15;         // latent dim
    const int half = lane >> 4;         // field half: 0 -> [0,13), 1 -> [13,26)

    const unsigned long long pol = mk_policy_keep();

    const int*   sp = sparse + b * FM_NFIELDS;
    const float* db = dense  + b * FM_NDENSE;
    const float* Vk = V + (size_t)k * FM_FEATNUM;

    const int base = half * 13;

    // ---- indices for this lane's 13 fields (broadcast within half-warp) ----
    int idx[13];
#pragma unroll
    for (int t = 0; t < 13; t++)
        idx[t] = FM_NDENSE + (base + t) * FM_PERFIELD + __ldg(sp + base + t);

    // ---- issue all 13 scattered V gathers up-front (independent, MLP=13) ----
    float g[13];
#pragma unroll
    for (int t = 0; t < 13; t++)
        g[t] = ldg_keep(Vk + idx[t], pol);

    // ---- first order: lane l covers sparse field l (l<26) + dense dim l (l<13) ----
    float fo = 0.0f;
    if (lane < FM_NFIELDS) {
        const int fidx = FM_NDENSE + lane * FM_PERFIELD + __ldg(sp + lane);
        fo = ldg_keep(w + fidx, pol);
    }
    if (lane < FM_NDENSE)
        fo = fmaf(__ldg(db + lane), __ldg(w + lane), fo);

    // ---- partial e_k / sq_k over this lane's 13 fields ----
    float e = 0.0f, s = 0.0f;
#pragma unroll
    for (int t = 0; t < 13; t++) {
        e += g[t];
        s  = fmaf(g[t], g[t], s);
    }

    // dense contribution, counted once per k (low half only); V[k,0:13] is hot
    if (half == 0) {
#pragma unroll
        for (int d = 0; d < FM_NDENSE; d++) {
            const float x  = __ldg(db + d);
            const float v  = __ldg(Vk + d);
            e = fmaf(x, v, e);
            const float xv = x * v;
            s = fmaf(xv, xv, s);
        }
    }

    // ---- combine the two field-halves per k BEFORE squaring ----
    const float E = e + __shfl_xor_sync(0xFFFFFFFFu, e, 16);
    const float S = s + __shfl_xor_sync(0xFFFFFFFFu, s, 16);

    float tot = fo;
    if (half == 0)                       // second-order term once per k
        tot = fmaf(0.5f, E * E - S, tot);

    // ---- full-warp sum: 16 second-order terms + 26 w terms + 13 dense terms ----
#pragma unroll
    for (int m = 16; m >= 1; m >>= 1)
        tot += __shfl_xor_sync(0xFFFFFFFFu, tot, m);

    if (lane == 0)
        out[b] = tot + __ldg(w0);
}

extern "C" void kernel_launch(void* const* d_in, const int* in_sizes, int n_in,
                              void* d_out, int out_size)
{
    const float* dense  = (const float*)d_in[0];
    const int*   sparse = (const int*)  d_in[1];
    const float* w0     = (const float*)d_in[2];
    const float* w      = (const float*)d_in[3];
    const float* V      = (const float*)d_in[4];
    float*       out    = (float*)d_out;

    const int total   = FM_BATCH * 32;          // one warp per row -> 131072 threads
    const int threads = 128;
    const int blocks  = total / threads;        // 1024 CTAs (~6.9/SM, balanced)
    fm_layer_kernel<<<blocks, threads>>>(dense, sparse, w0, w, V, out);
}